// round 1
// baseline (speedup 1.0000x reference)
#include <cuda_runtime.h>
#include <cstdint>

#define NB   8192
#define SS   64
#define NXX  4
#define NSF  5
#define HH   32
#define WPB  4      // warps (batch elements) per block
#define CH   8      // layer-2 time chunk
#define FULLMASK 0xffffffffu

static __device__ __forceinline__ float sigm(float x) {
    return __fdividef(1.0f, 1.0f + __expf(-x));
}
static __device__ __forceinline__ float tanhfast(float x) {
    float ax = fabsf(x);
    float e  = __expf(-2.0f * ax);
    float r  = __fdividef(1.0f - e, 1.0f + e);
    return copysignf(r, x);
}

__global__ void __launch_bounds__(WPB * 32)
lstm_fused(const float* __restrict__ x_main,   // [B,S,NX]
           const float* __restrict__ x_sfc,    // [B,NSF]
           const float* __restrict__ w_sfc1,   // [H,NSF]
           const float* __restrict__ b_sfc1,   // [H]
           const float* __restrict__ w_sfc2,   // [H,NSF]
           const float* __restrict__ b_sfc2,   // [H]
           const float* __restrict__ w_ih1,    // [4H,NX]
           const float* __restrict__ w_hh1,    // [4H,H]
           const float* __restrict__ b_ih1,    // [4H]
           const float* __restrict__ b_hh1,    // [4H]
           const float* __restrict__ w_ih2,    // [4H,H]
           const float* __restrict__ w_hh2,    // [4H,H]
           const float* __restrict__ b_ih2,    // [4H]
           const float* __restrict__ b_hh2,    // [4H]
           const float* __restrict__ w_out,    // [1,H]
           const float* __restrict__ b_out,    // [1]
           float* __restrict__ out)            // [B,S,1]
{
    extern __shared__ float smem[];
    float* s_wih2 = smem;                 // 4096
    float* s_whh2 = smem + 4096;          // 4096
    float* s_y    = smem + 8192;          // WPB * 64 * 32

    const int tid  = threadIdx.x;
    const int wid  = tid >> 5;
    const int lane = tid & 31;
    const int b    = blockIdx.x * WPB + wid;

    // Stage layer-2 weight matrices into shared (block-cooperative, coalesced)
    for (int i = tid; i < 4 * HH * HH; i += WPB * 32) {
        s_wih2[i] = w_ih2[i];
        s_whh2[i] = w_hh2[i];
    }
    __syncthreads();
    if (b >= NB) return;

    // ---------------- initial state from surface MLPs ----------------
    float h, c;
    {
        float sf[NSF];
        #pragma unroll
        for (int k = 0; k < NSF; ++k) sf[k] = x_sfc[b * NSF + k];
        float a1 = b_sfc1[lane];
        float a2 = b_sfc2[lane];
        #pragma unroll
        for (int k = 0; k < NSF; ++k) {
            a1 += sf[k] * w_sfc1[lane * NSF + k];
            a2 += sf[k] * w_sfc2[lane * NSF + k];
        }
        h = tanhfast(a1);
        c = tanhfast(a2);
    }

    // ---------------- layer-1 weights -> registers ----------------
    float w1[4][HH];     // w_hh1 rows (i,f,g,o) for this lane
    float wi1[4][NXX];
    float bias1[4];
    #pragma unroll
    for (int g = 0; g < 4; ++g) {
        const int row = g * HH + lane;
        #pragma unroll
        for (int k = 0; k < HH; k += 4) {
            float4 v = *(const float4*)(w_hh1 + row * HH + k);
            w1[g][k] = v.x; w1[g][k+1] = v.y; w1[g][k+2] = v.z; w1[g][k+3] = v.w;
        }
        float4 vi = *(const float4*)(w_ih1 + row * NXX);
        wi1[g][0] = vi.x; wi1[g][1] = vi.y; wi1[g][2] = vi.z; wi1[g][3] = vi.w;
        bias1[g] = b_ih1[row] + b_hh1[row];
    }

    float* yw = s_y + wid * (SS * HH);
    const float* xb = x_main + (size_t)b * (SS * NXX);

    // ---------------- layer 1: time-reversed scan ----------------
    // step t consumes original time s = 63-t, its h is y[s]
    #pragma unroll 1
    for (int t = 0; t < SS; ++t) {
        const int s = SS - 1 - t;
        const float4 xv = *(const float4*)(xb + s * NXX);
        float a0 = bias1[0] + xv.x*wi1[0][0] + xv.y*wi1[0][1] + xv.z*wi1[0][2] + xv.w*wi1[0][3];
        float a1 = bias1[1] + xv.x*wi1[1][0] + xv.y*wi1[1][1] + xv.z*wi1[1][2] + xv.w*wi1[1][3];
        float a2 = bias1[2] + xv.x*wi1[2][0] + xv.y*wi1[2][1] + xv.z*wi1[2][2] + xv.w*wi1[2][3];
        float a3 = bias1[3] + xv.x*wi1[3][0] + xv.y*wi1[3][1] + xv.z*wi1[3][2] + xv.w*wi1[3][3];
        #pragma unroll
        for (int k = 0; k < HH; ++k) {
            const float hk = __shfl_sync(FULLMASK, h, k);
            a0 += hk * w1[0][k];
            a1 += hk * w1[1][k];
            a2 += hk * w1[2][k];
            a3 += hk * w1[3][k];
        }
        const float ig = sigm(a0);
        const float fg = sigm(a1);
        const float gg = tanhfast(a2);
        const float og = sigm(a3);
        c = fg * c + ig * gg;
        h = og * tanhfast(c);
        yw[s * HH + lane] = h;
    }

    // ---------------- layer 2: forward scan, chunked ----------------
    float bias2[4];
    #pragma unroll
    for (int g = 0; g < 4; ++g) bias2[g] = b_ih2[g * HH + lane] + b_hh2[g * HH + lane];
    const float wo = w_out[lane];
    const float bo = b_out[0];

    float h2 = 0.0f, c2 = 0.0f;
    float* outb = out + (size_t)b * SS;

    #pragma unroll 1
    for (int chk = 0; chk < SS / CH; ++chk) {
        const int t0 = chk * CH;
        float w2[4][HH];

        // phase A: input projection xg2 for this chunk (w_ih2 in regs)
        #pragma unroll
        for (int g = 0; g < 4; ++g) {
            const int row = g * HH + lane;
            #pragma unroll
            for (int k = 0; k < HH; k += 4) {
                float4 v = *(const float4*)(s_wih2 + row * HH + k);
                w2[g][k] = v.x; w2[g][k+1] = v.y; w2[g][k+2] = v.z; w2[g][k+3] = v.w;
            }
        }
        float xg[CH][4];
        #pragma unroll
        for (int tt = 0; tt < CH; ++tt) {
            const float* yt = yw + (t0 + tt) * HH;
            float a0 = 0.f, a1 = 0.f, a2 = 0.f, a3 = 0.f;
            #pragma unroll
            for (int k = 0; k < HH; ++k) {
                const float yv = yt[k];   // smem broadcast
                a0 += yv * w2[0][k];
                a1 += yv * w2[1][k];
                a2 += yv * w2[2][k];
                a3 += yv * w2[3][k];
            }
            xg[tt][0] = a0; xg[tt][1] = a1; xg[tt][2] = a2; xg[tt][3] = a3;
        }

        // phase B: recurrence (w_hh2 reuses the same registers)
        #pragma unroll
        for (int g = 0; g < 4; ++g) {
            const int row = g * HH + lane;
            #pragma unroll
            for (int k = 0; k < HH; k += 4) {
                float4 v = *(const float4*)(s_whh2 + row * HH + k);
                w2[g][k] = v.x; w2[g][k+1] = v.y; w2[g][k+2] = v.z; w2[g][k+3] = v.w;
            }
        }
        #pragma unroll
        for (int tt = 0; tt < CH; ++tt) {
            float a0 = xg[tt][0] + bias2[0];
            float a1 = xg[tt][1] + bias2[1];
            float a2 = xg[tt][2] + bias2[2];
            float a3 = xg[tt][3] + bias2[3];
            #pragma unroll
            for (int k = 0; k < HH; ++k) {
                const float hk = __shfl_sync(FULLMASK, h2, k);
                a0 += hk * w2[0][k];
                a1 += hk * w2[1][k];
                a2 += hk * w2[2][k];
                a3 += hk * w2[3][k];
            }
            const float ig = sigm(a0);
            const float fg = sigm(a1);
            const float gg = tanhfast(a2);
            const float og = sigm(a3);
            c2 = fg * c2 + ig * gg;
            h2 = og * tanhfast(c2);

            // output head: out[b,t] = <h2, w_out> + b_out
            float po = h2 * wo;
            #pragma unroll
            for (int off = 16; off; off >>= 1)
                po += __shfl_xor_sync(FULLMASK, po, off);
            if (lane == 0) outb[t0 + tt] = po + bo;
        }
    }
}

extern "C" void kernel_launch(void* const* d_in, const int* in_sizes, int n_in,
                              void* d_out, int out_size)
{
    const float* x_main = (const float*)d_in[0];
    const float* x_sfc  = (const float*)d_in[1];
    const float* w_sfc1 = (const float*)d_in[2];
    const float* b_sfc1 = (const float*)d_in[3];
    const float* w_sfc2 = (const float*)d_in[4];
    const float* b_sfc2 = (const float*)d_in[5];
    const float* w_ih1  = (const float*)d_in[6];
    const float* w_hh1  = (const float*)d_in[7];
    const float* b_ih1  = (const float*)d_in[8];
    const float* b_hh1  = (const float*)d_in[9];
    const float* w_ih2  = (const float*)d_in[10];
    const float* w_hh2  = (const float*)d_in[11];
    const float* b_ih2  = (const float*)d_in[12];
    const float* b_hh2  = (const float*)d_in[13];
    const float* w_out  = (const float*)d_in[14];
    const float* b_out  = (const float*)d_in[15];
    float* out = (float*)d_out;

    const int smem_bytes = (4096 + 4096 + WPB * SS * HH) * (int)sizeof(float); // 64 KB
    static bool attr_set = false;
    if (!attr_set) {
        cudaFuncSetAttribute(lstm_fused, cudaFuncAttributeMaxDynamicSharedMemorySize, smem_bytes);
        attr_set = true;
    }

    const int blocks = NB / WPB;
    lstm_fused<<<blocks, WPB * 32, smem_bytes>>>(
        x_main, x_sfc, w_sfc1, b_sfc1, w_sfc2, b_sfc2,
        w_ih1, w_hh1, b_ih1, b_hh1,
        w_ih2, w_hh2, b_ih2, b_hh2,
        w_out, b_out, out);
}

// round 2
// speedup vs baseline: 1.8917x; 1.8917x over previous
#include <cuda_runtime.h>
#include <cstdint>

typedef unsigned long long u64;

#define NB   8192
#define SS   64
#define NXX  4
#define NSF  5
#define HH   32
#define WPB  4      // warps (batch elements) per block
#define CH   8      // layer-2 time chunk
#define FULLMASK 0xffffffffu

// ---------- packed f32x2 helpers ----------
static __device__ __forceinline__ u64 ffma2(u64 a, u64 b, u64 c) {
    u64 d;
    asm("fma.rn.f32x2 %0, %1, %2, %3;" : "=l"(d) : "l"(a), "l"(b), "l"(c));
    return d;
}
static __device__ __forceinline__ float hsum2(u64 v) {
    float x, y;
    asm("mov.b64 {%0, %1}, %2;" : "=f"(x), "=f"(y) : "l"(v));
    return x + y;
}
static __device__ __forceinline__ u64 pklo(float lo) {
    u64 r;
    asm("mov.b64 %0, {%1, %2};" : "=l"(r) : "f"(lo), "f"(0.0f));
    return r;
}

static __device__ __forceinline__ float sigm(float x) {
    return __fdividef(1.0f, 1.0f + __expf(-x));
}
static __device__ __forceinline__ float tanhfast(float x) {
    float ax = fabsf(x);
    float e  = __expf(-2.0f * ax);
    float r  = __fdividef(1.0f - e, 1.0f + e);
    return copysignf(r, x);
}

// Shared memory layout (floats):
//   [0,     8192)  w2t : transposed layer-2 weights as ulonglong2[(m*8+qq)*128 + row]
//   [8192, 12288)  w1t : transposed w_hh1 as ulonglong2[qq*128 + row]
//   [12288,20480)  y   : WPB * 64 * 32 layer-1 outputs
//   [20480,20736)  hb  : WPB * 2 * 32 h broadcast double-buffers
#define SMEM_FLOATS (8192 + 4096 + WPB*SS*HH + WPB*64)

__global__ void __launch_bounds__(WPB * 32)
lstm_fused2(const float* __restrict__ x_main,   // [B,S,NX]
            const float* __restrict__ x_sfc,    // [B,NSF]
            const float* __restrict__ w_sfc1,   // [H,NSF]
            const float* __restrict__ b_sfc1,   // [H]
            const float* __restrict__ w_sfc2,   // [H,NSF]
            const float* __restrict__ b_sfc2,   // [H]
            const float* __restrict__ w_ih1,    // [4H,NX]
            const float* __restrict__ w_hh1,    // [4H,H]
            const float* __restrict__ b_ih1,    // [4H]
            const float* __restrict__ b_hh1,    // [4H]
            const float* __restrict__ w_ih2,    // [4H,H]
            const float* __restrict__ w_hh2,    // [4H,H]
            const float* __restrict__ b_ih2,    // [4H]
            const float* __restrict__ b_hh2,    // [4H]
            const float* __restrict__ w_out,    // [1,H]
            const float* __restrict__ b_out,    // [1]
            float* __restrict__ out)            // [B,S,1]
{
    extern __shared__ float smem[];
    ulonglong2* w2t = (ulonglong2*)smem;               // [16][128] pairs-of-pairs
    ulonglong2* w1t = (ulonglong2*)(smem + 8192);      // [8][128]
    float* s_y  = smem + 8192 + 4096;
    float* s_hb = smem + 8192 + 4096 + WPB * SS * HH;

    const int tid  = threadIdx.x;
    const int wid  = tid >> 5;
    const int lane = tid & 31;
    const int b    = blockIdx.x * WPB + wid;

    // ---- stage transposed weights (conflict-free later reads) ----
    for (int i = tid; i < 16 * 128; i += WPB * 32) {
        const int m   = i >> 10;          // 0: w_ih2, 1: w_hh2
        const int qq  = (i >> 7) & 7;
        const int row = i & 127;
        const float* src = (m ? w_hh2 : w_ih2) + row * HH + qq * 4;
        w2t[i] = *(const ulonglong2*)src;
    }
    for (int i = tid; i < 8 * 128; i += WPB * 32) {
        const int qq  = i >> 7;
        const int row = i & 127;
        w1t[i] = *(const ulonglong2*)(w_hh1 + row * HH + qq * 4);
    }
    __syncthreads();

    // ---------------- initial state from surface MLPs ----------------
    float h, c;
    {
        float sf[NSF];
        #pragma unroll
        for (int k = 0; k < NSF; ++k) sf[k] = x_sfc[b * NSF + k];
        float a1 = b_sfc1[lane];
        float a2 = b_sfc2[lane];
        #pragma unroll
        for (int k = 0; k < NSF; ++k) {
            a1 += sf[k] * w_sfc1[lane * NSF + k];
            a2 += sf[k] * w_sfc2[lane * NSF + k];
        }
        h = tanhfast(a1);
        c = tanhfast(a2);
    }

    // ---------------- layer-1 weights -> registers (packed pairs) ----------------
    u64 whh[4][16];
    u64 wih[4][2];
    float bias1[4];
    #pragma unroll
    for (int g = 0; g < 4; ++g) {
        const int row = g * HH + lane;
        #pragma unroll
        for (int qq = 0; qq < 8; ++qq) {
            ulonglong2 v = w1t[qq * 128 + row];
            whh[g][2 * qq]     = v.x;
            whh[g][2 * qq + 1] = v.y;
        }
        ulonglong2 vi = *(const ulonglong2*)(w_ih1 + row * NXX);
        wih[g][0] = vi.x;
        wih[g][1] = vi.y;
        bias1[g] = b_ih1[row] + b_hh1[row];
    }

    float* yw = s_y + wid * (SS * HH);
    float* hb = s_hb + wid * 64;
    const float* xb = x_main + (size_t)b * (SS * NXX);

    // ---------------- layer 1: time-reversed scan ----------------
    hb[lane] = h;
    __syncwarp();
    int buf = 0;

    #pragma unroll 2
    for (int t = 0; t < SS; ++t) {
        const int s = SS - 1 - t;
        const ulonglong2 xv = *(const ulonglong2*)(xb + s * NXX);
        u64 a0 = pklo(bias1[0]);
        u64 a1 = pklo(bias1[1]);
        u64 a2 = pklo(bias1[2]);
        u64 a3 = pklo(bias1[3]);
        a0 = ffma2(xv.x, wih[0][0], a0); a0 = ffma2(xv.y, wih[0][1], a0);
        a1 = ffma2(xv.x, wih[1][0], a1); a1 = ffma2(xv.y, wih[1][1], a1);
        a2 = ffma2(xv.x, wih[2][0], a2); a2 = ffma2(xv.y, wih[2][1], a2);
        a3 = ffma2(xv.x, wih[3][0], a3); a3 = ffma2(xv.y, wih[3][1], a3);

        const ulonglong2* hp = (const ulonglong2*)(hb + buf * 32);
        #pragma unroll
        for (int q = 0; q < 8; ++q) {
            const ulonglong2 hv = hp[q];
            a0 = ffma2(hv.x, whh[0][2*q], a0); a0 = ffma2(hv.y, whh[0][2*q+1], a0);
            a1 = ffma2(hv.x, whh[1][2*q], a1); a1 = ffma2(hv.y, whh[1][2*q+1], a1);
            a2 = ffma2(hv.x, whh[2][2*q], a2); a2 = ffma2(hv.y, whh[2][2*q+1], a2);
            a3 = ffma2(hv.x, whh[3][2*q], a3); a3 = ffma2(hv.y, whh[3][2*q+1], a3);
        }

        const float ig = sigm(hsum2(a0));
        const float fg = sigm(hsum2(a1));
        const float gg = tanhfast(hsum2(a2));
        const float og = sigm(hsum2(a3));
        c = fg * c + ig * gg;
        h = og * tanhfast(c);
        yw[s * HH + lane] = h;
        hb[(buf ^ 1) * 32 + lane] = h;
        __syncwarp();
        buf ^= 1;
    }

    // ---------------- layer 2: forward scan, chunked ----------------
    float bias2[4];
    #pragma unroll
    for (int g = 0; g < 4; ++g)
        bias2[g] = b_ih2[g * HH + lane] + b_hh2[g * HH + lane];
    const float wo = w_out[lane];
    const float bo = b_out[0];

    float h2 = 0.0f, c2 = 0.0f;
    float* outb = out + (size_t)b * SS;

    hb[buf * 32 + lane] = 0.0f;
    __syncwarp();

    u64 w2r[4][16];
    float xg[CH][4];

    #pragma unroll 1
    for (int chk = 0; chk < SS / CH; ++chk) {
        const int t0 = chk * CH;

        // phase A: input projection for this chunk (w_ih2 in regs)
        #pragma unroll
        for (int g = 0; g < 4; ++g) {
            const int row = g * HH + lane;
            #pragma unroll
            for (int qq = 0; qq < 8; ++qq) {
                ulonglong2 v = w2t[qq * 128 + row];
                w2r[g][2*qq]   = v.x;
                w2r[g][2*qq+1] = v.y;
            }
        }
        #pragma unroll
        for (int tt = 0; tt < CH; ++tt) {
            const ulonglong2* yp = (const ulonglong2*)(yw + (t0 + tt) * HH);
            u64 a0 = 0ull, a1 = 0ull, a2 = 0ull, a3 = 0ull;
            #pragma unroll
            for (int q = 0; q < 8; ++q) {
                const ulonglong2 hv = yp[q];
                a0 = ffma2(hv.x, w2r[0][2*q], a0); a0 = ffma2(hv.y, w2r[0][2*q+1], a0);
                a1 = ffma2(hv.x, w2r[1][2*q], a1); a1 = ffma2(hv.y, w2r[1][2*q+1], a1);
                a2 = ffma2(hv.x, w2r[2][2*q], a2); a2 = ffma2(hv.y, w2r[2][2*q+1], a2);
                a3 = ffma2(hv.x, w2r[3][2*q], a3); a3 = ffma2(hv.y, w2r[3][2*q+1], a3);
            }
            xg[tt][0] = hsum2(a0);
            xg[tt][1] = hsum2(a1);
            xg[tt][2] = hsum2(a2);
            xg[tt][3] = hsum2(a3);
        }

        // phase B: recurrence (w_hh2 reuses the same registers)
        #pragma unroll
        for (int g = 0; g < 4; ++g) {
            const int row = g * HH + lane;
            #pragma unroll
            for (int qq = 0; qq < 8; ++qq) {
                ulonglong2 v = w2t[1024 + qq * 128 + row];
                w2r[g][2*qq]   = v.x;
                w2r[g][2*qq+1] = v.y;
            }
        }
        #pragma unroll
        for (int tt = 0; tt < CH; ++tt) {
            u64 a0 = pklo(xg[tt][0] + bias2[0]);
            u64 a1 = pklo(xg[tt][1] + bias2[1]);
            u64 a2 = pklo(xg[tt][2] + bias2[2]);
            u64 a3 = pklo(xg[tt][3] + bias2[3]);
            const ulonglong2* hp = (const ulonglong2*)(hb + buf * 32);
            #pragma unroll
            for (int q = 0; q < 8; ++q) {
                const ulonglong2 hv = hp[q];
                a0 = ffma2(hv.x, w2r[0][2*q], a0); a0 = ffma2(hv.y, w2r[0][2*q+1], a0);
                a1 = ffma2(hv.x, w2r[1][2*q], a1); a1 = ffma2(hv.y, w2r[1][2*q+1], a1);
                a2 = ffma2(hv.x, w2r[2][2*q], a2); a2 = ffma2(hv.y, w2r[2][2*q+1], a2);
                a3 = ffma2(hv.x, w2r[3][2*q], a3); a3 = ffma2(hv.y, w2r[3][2*q+1], a3);
            }
            const float ig = sigm(hsum2(a0));
            const float fg = sigm(hsum2(a1));
            const float gg = tanhfast(hsum2(a2));
            const float og = sigm(hsum2(a3));
            c2 = fg * c2 + ig * gg;
            h2 = og * tanhfast(c2);
            hb[(buf ^ 1) * 32 + lane] = h2;
            __syncwarp();
            buf ^= 1;

            // output head: out[b,t] = <h2, w_out> + b_out
            float po = h2 * wo;
            #pragma unroll
            for (int off = 16; off; off >>= 1)
                po += __shfl_xor_sync(FULLMASK, po, off);
            if (lane == 0) outb[t0 + tt] = po + bo;
        }
    }
}

extern "C" void kernel_launch(void* const* d_in, const int* in_sizes, int n_in,
                              void* d_out, int out_size)
{
    const float* x_main = (const float*)d_in[0];
    const float* x_sfc  = (const float*)d_in[1];
    const float* w_sfc1 = (const float*)d_in[2];
    const float* b_sfc1 = (const float*)d_in[3];
    const float* w_sfc2 = (const float*)d_in[4];
    const float* b_sfc2 = (const float*)d_in[5];
    const float* w_ih1  = (const float*)d_in[6];
    const float* w_hh1  = (const float*)d_in[7];
    const float* b_ih1  = (const float*)d_in[8];
    const float* b_hh1  = (const float*)d_in[9];
    const float* w_ih2  = (const float*)d_in[10];
    const float* w_hh2  = (const float*)d_in[11];
    const float* b_ih2  = (const float*)d_in[12];
    const float* b_hh2  = (const float*)d_in[13];
    const float* w_out  = (const float*)d_in[14];
    const float* b_out  = (const float*)d_in[15];
    float* out = (float*)d_out;

    const int smem_bytes = SMEM_FLOATS * (int)sizeof(float);  // ~83 KB
    static bool attr_set = false;
    if (!attr_set) {
        cudaFuncSetAttribute(lstm_fused2, cudaFuncAttributeMaxDynamicSharedMemorySize, smem_bytes);
        attr_set = true;
    }

    const int blocks = NB / WPB;
    lstm_fused2<<<blocks, WPB * 32, smem_bytes>>>(
        x_main, x_sfc, w_sfc1, b_sfc1, w_sfc2, b_sfc2,
        w_ih1, w_hh1, b_ih1, b_hh1,
        w_ih2, w_hh2, b_ih2, b_hh2,
        w_out, b_out, out);
}